// round 2
// baseline (speedup 1.0000x reference)
#include <cuda_runtime.h>
#include <cuda_bf16.h>
#include <cstdint>

// Problem constants
#define BQ 4
#define SQ 4096
#define DD 1024
#define MROWS (BQ*SQ)        // 16384

// GEMM tiling
#define BM 128
#define BN 128
#define BK 32
#define NTHREADS 256

// ---------------- static device scratch (allocation-free rule) ----------------
__device__ __nv_bfloat16 g_Q[(size_t)MROWS * DD];                 // 32 MB
__device__ __nv_bfloat16 g_K[(size_t)MROWS * DD];                 // 32 MB
__device__ __nv_bfloat16 g_V[(size_t)MROWS * DD];                 // 32 MB
__device__ float         g_G[(size_t)MROWS * DD];                 // 64 MB
__device__ float         g_S[(size_t)BQ * SQ * SQ];               // 256 MB
__device__ __nv_bfloat16 g_P[(size_t)BQ * SQ * SQ];               // 128 MB

// ---------------- mma helper ----------------
__device__ __forceinline__ void mma16816(float c[4], const uint32_t a[4], const uint32_t b[2]) {
    asm volatile(
        "mma.sync.aligned.m16n8k16.row.col.f32.bf16.bf16.f32 "
        "{%0,%1,%2,%3}, {%4,%5,%6,%7}, {%8,%9}, {%0,%1,%2,%3};\n"
        : "+f"(c[0]), "+f"(c[1]), "+f"(c[2]), "+f"(c[3])
        : "r"(a[0]), "r"(a[1]), "r"(a[2]), "r"(a[3]), "r"(b[0]), "r"(b[1]));
}

// Fragment load + compute core shared by all GEMMs.
// As[BM][BK+8], Bs[BN][BK+8]; warp layout 4(m) x 2(n); warp tile 32x64.
#define GEMM_COMPUTE(As, Bs, acc, wm, wn, g, t)                                        \
    _Pragma("unroll")                                                                  \
    for (int ks = 0; ks < BK; ks += 16) {                                              \
        uint32_t afr[2][4];                                                            \
        uint32_t bfr[8][2];                                                            \
        _Pragma("unroll")                                                              \
        for (int mi = 0; mi < 2; mi++) {                                               \
            int r0 = (wm)*32 + mi*16 + (g);                                            \
            afr[mi][0] = *(const uint32_t*)&As[r0    ][ks + 2*(t)];                    \
            afr[mi][1] = *(const uint32_t*)&As[r0 + 8][ks + 2*(t)];                    \
            afr[mi][2] = *(const uint32_t*)&As[r0    ][ks + 2*(t) + 8];                \
            afr[mi][3] = *(const uint32_t*)&As[r0 + 8][ks + 2*(t) + 8];                \
        }                                                                              \
        _Pragma("unroll")                                                              \
        for (int ni = 0; ni < 8; ni++) {                                               \
            int cb = (wn)*64 + ni*8 + (g);                                             \
            bfr[ni][0] = *(const uint32_t*)&Bs[cb][ks + 2*(t)];                        \
            bfr[ni][1] = *(const uint32_t*)&Bs[cb][ks + 2*(t) + 8];                    \
        }                                                                              \
        _Pragma("unroll")                                                              \
        for (int mi = 0; mi < 2; mi++)                                                 \
            _Pragma("unroll")                                                          \
            for (int ni = 0; ni < 8; ni++)                                             \
                mma16816(acc[mi][ni], afr[mi], bfr[ni]);                               \
    }

// ============================================================================
// Kernel 1: fused QKVG projections.  z = 0..3 picks target.
// Y = X @ W + b ;  Q/K/V stored bf16 ; G stored fp32 after sigmoid.
// ============================================================================
__global__ __launch_bounds__(NTHREADS)
void proj_kernel(const float* __restrict__ X,
                 const float* __restrict__ Wq, const float* __restrict__ bq,
                 const float* __restrict__ Wk, const float* __restrict__ bk,
                 const float* __restrict__ Wv, const float* __restrict__ bv,
                 const float* __restrict__ Wg, const float* __restrict__ bg)
{
    const int zb = blockIdx.z;
    const float* W    = (zb == 0) ? Wq : (zb == 1) ? Wk : (zb == 2) ? Wv : Wg;
    const float* bias = (zb == 0) ? bq : (zb == 1) ? bk : (zb == 2) ? bv : bg;

    const int m0 = blockIdx.y * BM;
    const int n0 = blockIdx.x * BN;

    __shared__ __nv_bfloat16 As[BM][BK + 8];
    __shared__ __nv_bfloat16 Bs[BN][BK + 8];

    const int tid  = threadIdx.x;
    const int lane = tid & 31;
    const int warp = tid >> 5;
    const int wm = warp & 3, wn = warp >> 2;
    const int g = lane >> 2, t = lane & 3;

    float acc[2][8][4] = {};

    for (int k0 = 0; k0 < DD; k0 += BK) {
        // A tile: X fp32 -> bf16.  128 rows x 32 cols = 1024 float4.
        #pragma unroll
        for (int i = 0; i < 4; i++) {
            int idx = tid + i * NTHREADS;
            int row = idx >> 3, c = idx & 7;
            const float4 v = *(const float4*)(X + (size_t)(m0 + row) * DD + k0 + c * 4);
            *(__nv_bfloat162*)&As[row][c * 4]     = __floats2bfloat162_rn(v.x, v.y);
            *(__nv_bfloat162*)&As[row][c * 4 + 2] = __floats2bfloat162_rn(v.z, v.w);
        }
        // B tile: W[k][n] fp32, transposed into Bs[n][k] as bf16.
        #pragma unroll
        for (int i = 0; i < 4; i++) {
            int idx = tid + i * NTHREADS;
            int rk = idx >> 5, c = idx & 31;
            const float4 v = *(const float4*)(W + (size_t)(k0 + rk) * DD + n0 + c * 4);
            Bs[c * 4 + 0][rk] = __float2bfloat16(v.x);
            Bs[c * 4 + 1][rk] = __float2bfloat16(v.y);
            Bs[c * 4 + 2][rk] = __float2bfloat16(v.z);
            Bs[c * 4 + 3][rk] = __float2bfloat16(v.w);
        }
        __syncthreads();
        GEMM_COMPUTE(As, Bs, acc, wm, wn, g, t)
        __syncthreads();
    }

    // Epilogue
    #pragma unroll
    for (int mi = 0; mi < 2; mi++) {
        #pragma unroll
        for (int ni = 0; ni < 8; ni++) {
            int row = m0 + wm * 32 + mi * 16 + g;
            int col = n0 + wn * 64 + ni * 8 + 2 * t;
            float b0 = bias[col], b1 = bias[col + 1];
            float c00 = acc[mi][ni][0] + b0, c01 = acc[mi][ni][1] + b1;
            float c10 = acc[mi][ni][2] + b0, c11 = acc[mi][ni][3] + b1;
            if (zb < 3) {
                __nv_bfloat16* O = (zb == 0) ? g_Q : (zb == 1) ? g_K : g_V;
                *(__nv_bfloat162*)&O[(size_t)row * DD + col]       = __floats2bfloat162_rn(c00, c01);
                *(__nv_bfloat162*)&O[(size_t)(row + 8) * DD + col] = __floats2bfloat162_rn(c10, c11);
            } else {
                float s00 = 1.f / (1.f + __expf(-c00));
                float s01 = 1.f / (1.f + __expf(-c01));
                float s10 = 1.f / (1.f + __expf(-c10));
                float s11 = 1.f / (1.f + __expf(-c11));
                *(float2*)&g_G[(size_t)row * DD + col]       = make_float2(s00, s01);
                *(float2*)&g_G[(size_t)(row + 8) * DD + col] = make_float2(s10, s11);
            }
        }
    }
}

// ============================================================================
// Kernel 2: scores[b,i,j] = (Q[b,i,:] . K[b,j,:]) / 32
// ============================================================================
__global__ __launch_bounds__(NTHREADS)
void scores_kernel()
{
    const int b  = blockIdx.z;
    const int m0 = blockIdx.y * BM;   // i
    const int n0 = blockIdx.x * BN;   // j

    const __nv_bfloat16* Qb = g_Q + (size_t)b * SQ * DD;
    const __nv_bfloat16* Kb = g_K + (size_t)b * SQ * DD;

    __shared__ __nv_bfloat16 As[BM][BK + 8];
    __shared__ __nv_bfloat16 Bs[BN][BK + 8];

    const int tid  = threadIdx.x;
    const int lane = tid & 31;
    const int warp = tid >> 5;
    const int wm = warp & 3, wn = warp >> 2;
    const int g = lane >> 2, t = lane & 3;

    float acc[2][8][4] = {};

    for (int k0 = 0; k0 < DD; k0 += BK) {
        #pragma unroll
        for (int i = 0; i < 2; i++) {           // A = Q tile (bf16)
            int idx = tid + i * NTHREADS;
            int row = idx >> 2, c = idx & 3;
            const uint4 v = *(const uint4*)(Qb + (size_t)(m0 + row) * DD + k0 + c * 8);
            *(uint2*)&As[row][c * 8]     = make_uint2(v.x, v.y);
            *(uint2*)&As[row][c * 8 + 4] = make_uint2(v.z, v.w);
        }
        #pragma unroll
        for (int i = 0; i < 2; i++) {           // B = K tile (bf16), natural layout
            int idx = tid + i * NTHREADS;
            int row = idx >> 2, c = idx & 3;
            const uint4 v = *(const uint4*)(Kb + (size_t)(n0 + row) * DD + k0 + c * 8);
            *(uint2*)&Bs[row][c * 8]     = make_uint2(v.x, v.y);
            *(uint2*)&Bs[row][c * 8 + 4] = make_uint2(v.z, v.w);
        }
        __syncthreads();
        GEMM_COMPUTE(As, Bs, acc, wm, wn, g, t)
        __syncthreads();
    }

    const float sc = 0.03125f; // 1/sqrt(1024)
    #pragma unroll
    for (int mi = 0; mi < 2; mi++) {
        #pragma unroll
        for (int ni = 0; ni < 8; ni++) {
            int row = m0 + wm * 32 + mi * 16 + g;
            int col = n0 + wn * 64 + ni * 8 + 2 * t;
            size_t base = ((size_t)b * SQ + row) * SQ + col;
            *(float2*)&g_S[base]            = make_float2(acc[mi][ni][0] * sc, acc[mi][ni][1] * sc);
            *(float2*)&g_S[base + 8ull*SQ]  = make_float2(acc[mi][ni][2] * sc, acc[mi][ni][3] * sc);
        }
    }
}

// ============================================================================
// Kernel 3: row softmax over 4096, writes bf16 attention weights
// ============================================================================
__global__ __launch_bounds__(NTHREADS)
void softmax_kernel()
{
    const size_t row = blockIdx.x;
    const float* s = g_S + row * SQ;
    __nv_bfloat16* p = g_P + row * SQ;

    const int tid = threadIdx.x;
    const int lane = tid & 31, warp = tid >> 5;

    float v[16];
    float m = -1e30f;
    #pragma unroll
    for (int i = 0; i < 16; i++) { v[i] = s[tid + i * NTHREADS]; m = fmaxf(m, v[i]); }

    __shared__ float red_m[8], red_s[8];
    #pragma unroll
    for (int o = 16; o; o >>= 1) m = fmaxf(m, __shfl_xor_sync(0xffffffffu, m, o));
    if (lane == 0) red_m[warp] = m;
    __syncthreads();
    float bm = -1e30f;
    #pragma unroll
    for (int i = 0; i < 8; i++) bm = fmaxf(bm, red_m[i]);

    float sum = 0.f;
    #pragma unroll
    for (int i = 0; i < 16; i++) { v[i] = __expf(v[i] - bm); sum += v[i]; }
    #pragma unroll
    for (int o = 16; o; o >>= 1) sum += __shfl_xor_sync(0xffffffffu, sum, o);
    if (lane == 0) red_s[warp] = sum;
    __syncthreads();
    float bs = 0.f;
    #pragma unroll
    for (int i = 0; i < 8; i++) bs += red_s[i];

    const float inv = 1.f / bs;
    #pragma unroll
    for (int i = 0; i < 16; i++) p[tid + i * NTHREADS] = __float2bfloat16(v[i] * inv);
}

// ============================================================================
// Kernel 4: out = P @ V ; y = g*out + x  (final epilogue, fp32 output)
// ============================================================================
__global__ __launch_bounds__(NTHREADS)
void out_kernel(const float* __restrict__ X, float* __restrict__ Y)
{
    const int b  = blockIdx.z;
    const int m0 = blockIdx.y * BM;   // i (per batch)
    const int n0 = blockIdx.x * BN;   // f

    const __nv_bfloat16* Pb = g_P + (size_t)b * SQ * SQ;
    const __nv_bfloat16* Vb = g_V + (size_t)b * SQ * DD;

    __shared__ __nv_bfloat16 As[BM][BK + 8];
    __shared__ __nv_bfloat16 Bs[BN][BK + 8];

    const int tid  = threadIdx.x;
    const int lane = tid & 31;
    const int warp = tid >> 5;
    const int wm = warp & 3, wn = warp >> 2;
    const int g = lane >> 2, t = lane & 3;

    float acc[2][8][4] = {};

    for (int k0 = 0; k0 < SQ; k0 += BK) {
        #pragma unroll
        for (int i = 0; i < 2; i++) {           // A = P tile (bf16), lda = SQ
            int idx = tid + i * NTHREADS;
            int row = idx >> 2, c = idx & 3;
            const uint4 v = *(const uint4*)(Pb + (size_t)(m0 + row) * SQ + k0 + c * 8);
            *(uint2*)&As[row][c * 8]     = make_uint2(v.x, v.y);
            *(uint2*)&As[row][c * 8 + 4] = make_uint2(v.z, v.w);
        }
        // B = V tile transposed: Bs[f][j] = V[k0+j][n0+f]
        #pragma unroll
        for (int i = 0; i < 2; i++) {
            int idx = tid + i * NTHREADS;       // 512 uint4 = 32 rows x 16
            int rj = idx >> 4, c = idx & 15;
            const uint4 v = *(const uint4*)(Vb + (size_t)(k0 + rj) * DD + n0 + c * 8);
            uint32_t ws[4] = {v.x, v.y, v.z, v.w};
            #pragma unroll
            for (int e = 0; e < 4; e++) {
                Bs[c * 8 + e * 2    ][rj] = __ushort_as_bfloat16((unsigned short)(ws[e] & 0xffff));
                Bs[c * 8 + e * 2 + 1][rj] = __ushort_as_bfloat16((unsigned short)(ws[e] >> 16));
            }
        }
        __syncthreads();
        GEMM_COMPUTE(As, Bs, acc, wm, wn, g, t)
        __syncthreads();
    }

    #pragma unroll
    for (int mi = 0; mi < 2; mi++) {
        #pragma unroll
        for (int ni = 0; ni < 8; ni++) {
            int rl  = m0 + wm * 32 + mi * 16 + g;
            int col = n0 + wn * 64 + ni * 8 + 2 * t;
            size_t gr0 = ((size_t)b * SQ + rl) * DD + col;
            size_t gr1 = ((size_t)b * SQ + rl + 8) * DD + col;
            float2 gv0 = *(const float2*)&g_G[gr0];
            float2 xv0 = *(const float2*)&X[gr0];
            float2 gv1 = *(const float2*)&g_G[gr1];
            float2 xv1 = *(const float2*)&X[gr1];
            *(float2*)&Y[gr0] = make_float2(gv0.x * acc[mi][ni][0] + xv0.x,
                                            gv0.y * acc[mi][ni][1] + xv0.y);
            *(float2*)&Y[gr1] = make_float2(gv1.x * acc[mi][ni][2] + xv1.x,
                                            gv1.y * acc[mi][ni][3] + xv1.y);
        }
    }
}

// ============================================================================
extern "C" void kernel_launch(void* const* d_in, const int* in_sizes, int n_in,
                              void* d_out, int out_size)
{
    const float* x  = (const float*)d_in[0];
    const float* Wq = (const float*)d_in[1];
    const float* bq = (const float*)d_in[2];
    const float* Wk = (const float*)d_in[3];
    const float* bk = (const float*)d_in[4];
    const float* Wv = (const float*)d_in[5];
    const float* bv = (const float*)d_in[6];
    const float* Wg = (const float*)d_in[7];
    const float* bg = (const float*)d_in[8];
    float* y = (float*)d_out;

    dim3 blk(NTHREADS);
    proj_kernel<<<dim3(DD / BN, MROWS / BM, 4), blk>>>(x, Wq, bq, Wk, bk, Wv, bv, Wg, bg);
    scores_kernel<<<dim3(SQ / BN, SQ / BM, 4), blk>>>();
    softmax_kernel<<<MROWS, blk>>>();
    out_kernel<<<dim3(DD / BN, SQ / BM, 4), blk>>>(x, y);
}

// round 3
// speedup vs baseline: 2.4817x; 2.4817x over previous
#include <cuda_runtime.h>
#include <cuda_bf16.h>
#include <cstdint>

// Problem constants
#define BQ 4
#define SQ 4096
#define DD 1024
#define MROWS (BQ*SQ)        // 16384

// GEMM tiling
#define BM 128
#define BN 128
#define BK 32
#define NTHREADS 256
#define SLDA 40              // smem row stride in halves (32 data + 8 pad = 80B)

// ---------------- static device scratch (allocation-free rule) ----------------
__device__ __nv_bfloat16 g_X [(size_t)MROWS * DD];        // 32 MB  (bf16 X)
__device__ __nv_bfloat16 g_Wt[4ull * DD * DD];            //  8 MB  (bf16 W^T, [z][n][k])
__device__ __nv_bfloat16 g_Q [(size_t)MROWS * DD];        // 32 MB
__device__ __nv_bfloat16 g_K [(size_t)MROWS * DD];        // 32 MB
__device__ __nv_bfloat16 g_V [(size_t)MROWS * DD];        // 32 MB
__device__ __nv_bfloat16 g_Vt[(size_t)BQ * DD * SQ];      // 32 MB  (V^T per batch, [b][f][j])
__device__ float         g_G [(size_t)MROWS * DD];        // 64 MB
__device__ float         g_S [(size_t)BQ * SQ * SQ];      // 256 MB
__device__ __nv_bfloat16 g_P [(size_t)BQ * SQ * SQ];      // 128 MB

// ---------------- low-level helpers ----------------
__device__ __forceinline__ uint32_t smem_u32(const void* p) {
    return (uint32_t)__cvta_generic_to_shared(p);
}
__device__ __forceinline__ void cp16(uint32_t dst, const void* src) {
    asm volatile("cp.async.cg.shared.global [%0], [%1], 16;\n" :: "r"(dst), "l"(src));
}
__device__ __forceinline__ void cp_commit() {
    asm volatile("cp.async.commit_group;\n");
}
template<int N> __device__ __forceinline__ void cp_wait() {
    asm volatile("cp.async.wait_group %0;\n" :: "n"(N));
}
__device__ __forceinline__ void ldsm4(uint32_t& r0, uint32_t& r1, uint32_t& r2, uint32_t& r3, uint32_t a) {
    asm volatile("ldmatrix.sync.aligned.m8n8.x4.shared.b16 {%0,%1,%2,%3}, [%4];\n"
                 : "=r"(r0), "=r"(r1), "=r"(r2), "=r"(r3) : "r"(a));
}
__device__ __forceinline__ void mma16816(float c[4], const uint32_t a[4], const uint32_t b[2]) {
    asm volatile(
        "mma.sync.aligned.m16n8k16.row.col.f32.bf16.bf16.f32 "
        "{%0,%1,%2,%3}, {%4,%5,%6,%7}, {%8,%9}, {%0,%1,%2,%3};\n"
        : "+f"(c[0]), "+f"(c[1]), "+f"(c[2]), "+f"(c[3])
        : "r"(a[0]), "r"(a[1]), "r"(a[2]), "r"(a[3]), "r"(b[0]), "r"(b[1]));
}

struct Smem {
    __nv_bfloat16 A[2][BM][SLDA];
    __nv_bfloat16 B[2][BN][SLDA];
};
#define BUF_STRIDE (BM * SLDA * 2)   // bytes per buffer = 10240

// ============================================================================
// Shared GEMM mainloop: C[128,128] += A[128,K] * B[128,K]^T (both k-contiguous
// bf16 in gmem).  Double-buffered cp.async + ldmatrix fragments.
// Warp layout 4(m) x 2(n); warp tile 32x64.
// ============================================================================
__device__ __forceinline__ void gemm_main(
    const __nv_bfloat16* __restrict__ Ag, size_t lda,
    const __nv_bfloat16* __restrict__ Bg, size_t ldb,
    int kTiles, Smem* sm, float acc[2][8][4])
{
    const int tid  = threadIdx.x;
    const int lane = tid & 31;
    const int warp = tid >> 5;
    const int wm = warp & 3, wn = warp >> 2;

    const uint32_t aBase = smem_u32(&sm->A[0][0][0]);
    const uint32_t bBase = smem_u32(&sm->B[0][0][0]);

    // ldmatrix lane addresses (buffer 0, ks = 0)
    // A x4 groups: (rows 0-7, k0) (rows 8-15, k0) (rows 0-7, k8) (rows 8-15, k8)
    const uint32_t aFrag0 = aBase +
        (uint32_t)(((wm * 32 + (lane & 15)) * SLDA + (lane >> 4) * 8) * 2);
    // B x4 groups: (n 0-7, k0) (n 0-7, k8) (n 8-15, k0) (n 8-15, k8)
    const uint32_t bFrag0 = bBase +
        (uint32_t)(((wn * 64 + ((lane >> 4) << 3) + (lane & 7)) * SLDA + ((lane >> 3) & 1) * 8) * 2);

    // cp.async: 512 16B chunks per tile, 2 per thread
    const int c0row = tid >> 2, c0off = (tid & 3) * 8;
    const int c1row = (tid + 256) >> 2, c1off = ((tid + 256) & 3) * 8;
    const uint32_t aDst0 = aBase + (uint32_t)((c0row * SLDA + c0off) * 2);
    const uint32_t aDst1 = aBase + (uint32_t)((c1row * SLDA + c1off) * 2);
    const uint32_t bDst0 = bBase + (uint32_t)((c0row * SLDA + c0off) * 2);
    const uint32_t bDst1 = bBase + (uint32_t)((c1row * SLDA + c1off) * 2);

    auto issue = [&](int kt) {
        const uint32_t bo = (kt & 1) * BUF_STRIDE;
        const size_t k0 = (size_t)kt * BK;
        cp16(aDst0 + bo, Ag + (size_t)c0row * lda + k0 + c0off);
        cp16(aDst1 + bo, Ag + (size_t)c1row * lda + k0 + c1off);
        cp16(bDst0 + bo, Bg + (size_t)c0row * ldb + k0 + c0off);
        cp16(bDst1 + bo, Bg + (size_t)c1row * ldb + k0 + c1off);
        cp_commit();
    };

    issue(0);
    for (int kt = 0; kt < kTiles; kt++) {
        if (kt + 1 < kTiles) { issue(kt + 1); cp_wait<1>(); }
        else                 { cp_wait<0>(); }
        __syncthreads();

        const uint32_t bo = (kt & 1) * BUF_STRIDE;
        #pragma unroll
        for (int ks = 0; ks < BK; ks += 16) {
            uint32_t afr[2][4];
            #pragma unroll
            for (int mi = 0; mi < 2; mi++)
                ldsm4(afr[mi][0], afr[mi][1], afr[mi][2], afr[mi][3],
                      aFrag0 + bo + (uint32_t)((mi * 16 * SLDA + ks) * 2));
            uint32_t bfr[8][2];
            #pragma unroll
            for (int nj = 0; nj < 4; nj++)
                ldsm4(bfr[2*nj][0], bfr[2*nj][1], bfr[2*nj+1][0], bfr[2*nj+1][1],
                      bFrag0 + bo + (uint32_t)((nj * 16 * SLDA + ks) * 2));
            #pragma unroll
            for (int mi = 0; mi < 2; mi++)
                #pragma unroll
                for (int ni = 0; ni < 8; ni++)
                    mma16816(acc[mi][ni], afr[mi], bfr[ni]);
        }
        __syncthreads();
    }
}

// ============================================================================
// Prep kernels
// ============================================================================
__global__ __launch_bounds__(NTHREADS)
void cvt_x_kernel(const float* __restrict__ X)
{
    size_t i = ((size_t)blockIdx.x * NTHREADS + threadIdx.x) * 8;
    float4 a = *(const float4*)(X + i);
    float4 b = *(const float4*)(X + i + 4);
    __nv_bfloat162 o0 = __floats2bfloat162_rn(a.x, a.y);
    __nv_bfloat162 o1 = __floats2bfloat162_rn(a.z, a.w);
    __nv_bfloat162 o2 = __floats2bfloat162_rn(b.x, b.y);
    __nv_bfloat162 o3 = __floats2bfloat162_rn(b.z, b.w);
    uint4 pack;
    pack.x = *(uint32_t*)&o0; pack.y = *(uint32_t*)&o1;
    pack.z = *(uint32_t*)&o2; pack.w = *(uint32_t*)&o3;
    *(uint4*)(g_X + i) = pack;
}

// W[k][n] fp32 -> g_Wt[z][n][k] bf16 (32x32 smem tile transpose)
__global__ __launch_bounds__(256)
void cvt_w_kernel(const float* __restrict__ Wq, const float* __restrict__ Wk,
                  const float* __restrict__ Wv, const float* __restrict__ Wg)
{
    const int z = blockIdx.z;
    const float* W = (z == 0) ? Wq : (z == 1) ? Wk : (z == 2) ? Wv : Wg;
    __shared__ __nv_bfloat16 t[32][33];
    const int n0 = blockIdx.x * 32, k0 = blockIdx.y * 32;
    const int tx = threadIdx.x & 31, ty = threadIdx.x >> 5;  // 32 x 8
    #pragma unroll
    for (int r = ty; r < 32; r += 8)
        t[r][tx] = __float2bfloat16(W[(size_t)(k0 + r) * DD + n0 + tx]);
    __syncthreads();
    #pragma unroll
    for (int r = ty; r < 32; r += 8)
        g_Wt[(size_t)z * DD * DD + (size_t)(n0 + r) * DD + k0 + tx] = t[tx][r];
}

// g_V[b*S+j][f] -> g_Vt[b][f][j]
__global__ __launch_bounds__(256)
void cvt_v_kernel()
{
    const int b = blockIdx.z;
    __shared__ __nv_bfloat16 t[32][33];
    const int j0 = blockIdx.x * 32, f0 = blockIdx.y * 32;
    const int tx = threadIdx.x & 31, ty = threadIdx.x >> 5;
    #pragma unroll
    for (int r = ty; r < 32; r += 8)
        t[r][tx] = g_V[((size_t)b * SQ + j0 + r) * DD + f0 + tx];
    __syncthreads();
    #pragma unroll
    for (int r = ty; r < 32; r += 8)
        g_Vt[(size_t)b * DD * SQ + (size_t)(f0 + r) * SQ + j0 + tx] = t[tx][r];
}

// ============================================================================
// Kernel 1: fused QKVG projections (z picks target).
// ============================================================================
__global__ __launch_bounds__(NTHREADS)
void proj_kernel(const float* __restrict__ bq, const float* __restrict__ bk,
                 const float* __restrict__ bv, const float* __restrict__ bg)
{
    const int zb = blockIdx.z;
    const float* bias = (zb == 0) ? bq : (zb == 1) ? bk : (zb == 2) ? bv : bg;

    const int m0 = blockIdx.y * BM;
    const int n0 = blockIdx.x * BN;

    __shared__ Smem sm;
    float acc[2][8][4] = {};

    gemm_main(g_X + (size_t)m0 * DD, DD,
              g_Wt + (size_t)zb * DD * DD + (size_t)n0 * DD, DD,
              DD / BK, &sm, acc);

    const int lane = threadIdx.x & 31, warp = threadIdx.x >> 5;
    const int wm = warp & 3, wn = warp >> 2;
    const int g = lane >> 2, t = lane & 3;

    #pragma unroll
    for (int mi = 0; mi < 2; mi++) {
        #pragma unroll
        for (int ni = 0; ni < 8; ni++) {
            int row = m0 + wm * 32 + mi * 16 + g;
            int col = n0 + wn * 64 + ni * 8 + 2 * t;
            float b0 = bias[col], b1 = bias[col + 1];
            float c00 = acc[mi][ni][0] + b0, c01 = acc[mi][ni][1] + b1;
            float c10 = acc[mi][ni][2] + b0, c11 = acc[mi][ni][3] + b1;
            if (zb < 3) {
                __nv_bfloat16* O = (zb == 0) ? g_Q : (zb == 1) ? g_K : g_V;
                *(__nv_bfloat162*)&O[(size_t)row * DD + col]       = __floats2bfloat162_rn(c00, c01);
                *(__nv_bfloat162*)&O[(size_t)(row + 8) * DD + col] = __floats2bfloat162_rn(c10, c11);
            } else {
                float s00 = 1.f / (1.f + __expf(-c00));
                float s01 = 1.f / (1.f + __expf(-c01));
                float s10 = 1.f / (1.f + __expf(-c10));
                float s11 = 1.f / (1.f + __expf(-c11));
                *(float2*)&g_G[(size_t)row * DD + col]       = make_float2(s00, s01);
                *(float2*)&g_G[(size_t)(row + 8) * DD + col] = make_float2(s10, s11);
            }
        }
    }
}

// ============================================================================
// Kernel 2: scores = Q K^T / 32
// ============================================================================
__global__ __launch_bounds__(NTHREADS)
void scores_kernel()
{
    const int b  = blockIdx.z;
    const int m0 = blockIdx.y * BM;
    const int n0 = blockIdx.x * BN;

    __shared__ Smem sm;
    float acc[2][8][4] = {};

    gemm_main(g_Q + (size_t)b * SQ * DD + (size_t)m0 * DD, DD,
              g_K + (size_t)b * SQ * DD + (size_t)n0 * DD, DD,
              DD / BK, &sm, acc);

    const int lane = threadIdx.x & 31, warp = threadIdx.x >> 5;
    const int wm = warp & 3, wn = warp >> 2;
    const int g = lane >> 2, t = lane & 3;

    const float sc = 0.03125f;
    #pragma unroll
    for (int mi = 0; mi < 2; mi++) {
        #pragma unroll
        for (int ni = 0; ni < 8; ni++) {
            int row = m0 + wm * 32 + mi * 16 + g;
            int col = n0 + wn * 64 + ni * 8 + 2 * t;
            size_t base = ((size_t)b * SQ + row) * SQ + col;
            *(float2*)&g_S[base]           = make_float2(acc[mi][ni][0] * sc, acc[mi][ni][1] * sc);
            *(float2*)&g_S[base + 8ull*SQ] = make_float2(acc[mi][ni][2] * sc, acc[mi][ni][3] * sc);
        }
    }
}

// ============================================================================
// Kernel 3: row softmax over 4096, writes bf16 attention weights
// ============================================================================
__global__ __launch_bounds__(NTHREADS)
void softmax_kernel()
{
    const size_t row = blockIdx.x;
    const float* s = g_S + row * SQ;
    __nv_bfloat16* p = g_P + row * SQ;

    const int tid = threadIdx.x;
    const int lane = tid & 31, warp = tid >> 5;

    float v[16];
    float m = -1e30f;
    #pragma unroll
    for (int i = 0; i < 16; i++) { v[i] = s[tid + i * NTHREADS]; m = fmaxf(m, v[i]); }

    __shared__ float red_m[8], red_s[8];
    #pragma unroll
    for (int o = 16; o; o >>= 1) m = fmaxf(m, __shfl_xor_sync(0xffffffffu, m, o));
    if (lane == 0) red_m[warp] = m;
    __syncthreads();
    float bm = -1e30f;
    #pragma unroll
    for (int i = 0; i < 8; i++) bm = fmaxf(bm, red_m[i]);

    float sum = 0.f;
    #pragma unroll
    for (int i = 0; i < 16; i++) { v[i] = __expf(v[i] - bm); sum += v[i]; }
    #pragma unroll
    for (int o = 16; o; o >>= 1) sum += __shfl_xor_sync(0xffffffffu, sum, o);
    if (lane == 0) red_s[warp] = sum;
    __syncthreads();
    float bs = 0.f;
    #pragma unroll
    for (int i = 0; i < 8; i++) bs += red_s[i];

    const float inv = 1.f / bs;
    #pragma unroll
    for (int i = 0; i < 16; i++) p[tid + i * NTHREADS] = __float2bfloat16(v[i] * inv);
}

// ============================================================================
// Kernel 4: out = P @ V ; y = g*out + x
// ============================================================================
__global__ __launch_bounds__(NTHREADS)
void out_kernel(const float* __restrict__ X, float* __restrict__ Y)
{
    const int b  = blockIdx.z;
    const int m0 = blockIdx.y * BM;
    const int n0 = blockIdx.x * BN;

    __shared__ Smem sm;
    float acc[2][8][4] = {};

    gemm_main(g_P + (size_t)b * SQ * SQ + (size_t)m0 * SQ, SQ,
              g_Vt + (size_t)b * DD * SQ + (size_t)n0 * SQ, SQ,
              SQ / BK, &sm, acc);

    const int lane = threadIdx.x & 31, warp = threadIdx.x >> 5;
    const int wm = warp & 3, wn = warp >> 2;
    const int g = lane >> 2, t = lane & 3;

    #pragma unroll
    for (int mi = 0; mi < 2; mi++) {
        #pragma unroll
        for (int ni = 0; ni < 8; ni++) {
            int rl  = m0 + wm * 32 + mi * 16 + g;
            int col = n0 + wn * 64 + ni * 8 + 2 * t;
            size_t gr0 = ((size_t)b * SQ + rl) * DD + col;
            size_t gr1 = ((size_t)b * SQ + rl + 8) * DD + col;
            float2 gv0 = *(const float2*)&g_G[gr0];
            float2 xv0 = *(const float2*)&X[gr0];
            float2 gv1 = *(const float2*)&g_G[gr1];
            float2 xv1 = *(const float2*)&X[gr1];
            *(float2*)&Y[gr0] = make_float2(gv0.x * acc[mi][ni][0] + xv0.x,
                                            gv0.y * acc[mi][ni][1] + xv0.y);
            *(float2*)&Y[gr1] = make_float2(gv1.x * acc[mi][ni][2] + xv1.x,
                                            gv1.y * acc[mi][ni][3] + xv1.y);
        }
    }
}

// ============================================================================
extern "C" void kernel_launch(void* const* d_in, const int* in_sizes, int n_in,
                              void* d_out, int out_size)
{
    const float* x  = (const float*)d_in[0];
    const float* Wq = (const float*)d_in[1];
    const float* bq = (const float*)d_in[2];
    const float* Wk = (const float*)d_in[3];
    const float* bk = (const float*)d_in[4];
    const float* Wv = (const float*)d_in[5];
    const float* bv = (const float*)d_in[6];
    const float* Wg = (const float*)d_in[7];
    const float* bg = (const float*)d_in[8];
    float* y = (float*)d_out;

    dim3 blk(NTHREADS);
    cvt_x_kernel<<<(MROWS * DD) / (NTHREADS * 8), blk>>>(x);
    cvt_w_kernel<<<dim3(DD / 32, DD / 32, 4), dim3(256)>>>(Wq, Wk, Wv, Wg);
    proj_kernel<<<dim3(DD / BN, MROWS / BM, 4), blk>>>(bq, bk, bv, bg);
    cvt_v_kernel<<<dim3(SQ / 32, DD / 32, BQ), dim3(256)>>>();
    scores_kernel<<<dim3(SQ / BN, SQ / BM, 4), blk>>>();
    softmax_kernel<<<MROWS, blk>>>();
    out_kernel<<<dim3(DD / BN, SQ / BM, 4), blk>>>(x, y);
}

// round 8
// speedup vs baseline: 3.4511x; 1.3907x over previous
#include <cuda_runtime.h>
#include <cuda_bf16.h>
#include <cstdint>

// Problem constants
#define BQ 4
#define SQ 4096
#define DD 1024
#define MROWS (BQ*SQ)        // 16384

// GEMM tiling
#define BM 128
#define BN 128
#define BK 64
#define NTH 256
#define STAGES 3
#define TILE_B 16384         // one operand tile: 128 rows x 128 bytes
#define STAGE_B 32768        // A + B
#define SMEM_B (STAGES*STAGE_B)   // 96 KB

// ---------------- static device scratch (allocation-free rule) ----------------
__device__ __nv_bfloat16 g_X [(size_t)MROWS * DD];        // bf16 X
__device__ __nv_bfloat16 g_Wt[4ull * DD * DD];            // bf16 W^T [z][n][k]
__device__ __nv_bfloat16 g_Q [(size_t)MROWS * DD];
__device__ __nv_bfloat16 g_K [(size_t)MROWS * DD];
__device__ __nv_bfloat16 g_V [(size_t)MROWS * DD];
__device__ __nv_bfloat16 g_Vt[(size_t)BQ * DD * SQ];      // V^T [b][f][j]
__device__ float         g_G [(size_t)MROWS * DD];
__device__ __nv_bfloat16 g_S [(size_t)BQ * SQ * SQ];      // bf16 scores
__device__ __nv_bfloat16 g_P [(size_t)BQ * SQ * SQ];      // bf16 attn weights

// ---------------- low-level helpers ----------------
__device__ __forceinline__ uint32_t smem_u32(const void* p) {
    return (uint32_t)__cvta_generic_to_shared(p);
}
__device__ __forceinline__ void cp16(uint32_t dst, const void* src) {
    asm volatile("cp.async.cg.shared.global [%0], [%1], 16;\n" :: "r"(dst), "l"(src));
}
__device__ __forceinline__ void cp_commit() {
    asm volatile("cp.async.commit_group;\n");
}
template<int N> __device__ __forceinline__ void cp_wait() {
    asm volatile("cp.async.wait_group %0;\n" :: "n"(N));
}
__device__ __forceinline__ void ldsm4(uint32_t& r0, uint32_t& r1, uint32_t& r2, uint32_t& r3, uint32_t a) {
    asm volatile("ldmatrix.sync.aligned.m8n8.x4.shared.b16 {%0,%1,%2,%3}, [%4];\n"
                 : "=r"(r0), "=r"(r1), "=r"(r2), "=r"(r3) : "r"(a));
}
__device__ __forceinline__ void mma16816(float c[4], const uint32_t a[4], const uint32_t b[2]) {
    asm volatile(
        "mma.sync.aligned.m16n8k16.row.col.f32.bf16.bf16.f32 "
        "{%0,%1,%2,%3}, {%4,%5,%6,%7}, {%8,%9}, {%0,%1,%2,%3};\n"
        : "+f"(c[0]), "+f"(c[1]), "+f"(c[2]), "+f"(c[3])
        : "r"(a[0]), "r"(a[1]), "r"(a[2]), "r"(a[3]), "r"(b[0]), "r"(b[1]));
}

// ============================================================================
// GEMM mainloop: C[128,128] = A[128,K] @ B[128,K]^T, bf16 K-major operands.
// 3-stage cp.async pipeline, XOR-swizzled smem (128B rows), ldmatrix frags.
// Warp layout 4(m) x 2(n); warp tile 32x64.
// ============================================================================
__device__ __forceinline__ void gemm_main(
    const __nv_bfloat16* __restrict__ Ag, size_t lda,
    const __nv_bfloat16* __restrict__ Bg, size_t ldb,
    int kTiles, float acc[2][8][4])
{
    extern __shared__ char smem[];
    const int tid  = threadIdx.x;
    const int lane = tid & 31;
    const int warp = tid >> 5;
    const int wm = warp & 3, wn = warp >> 2;
    const uint32_t base = smem_u32(smem);

    // cp.async per-thread mapping: 4 chunks per operand per stage
    uint32_t swDst[4];
    int rowIdx[4], uIdx[4];
    #pragma unroll
    for (int i = 0; i < 4; i++) {
        int id = tid + i * NTH;            // 0..1023
        int row = id >> 3, u = id & 7;
        rowIdx[i] = row; uIdx[i] = u;
        uint32_t boff = (uint32_t)(row * 128 + u * 16);
        swDst[i] = boff ^ ((boff >> 3) & 0x70);
    }

    auto issue = [&](int kt) {
        const uint32_t so = (uint32_t)(kt % STAGES) * STAGE_B;
        const size_t k0 = (size_t)kt * BK;
        #pragma unroll
        for (int i = 0; i < 4; i++) {
            cp16(base + so + swDst[i],
                 Ag + (size_t)rowIdx[i] * lda + k0 + uIdx[i] * 8);
            cp16(base + so + TILE_B + swDst[i],
                 Bg + (size_t)rowIdx[i] * ldb + k0 + uIdx[i] * 8);
        }
        cp_commit();
    };

    // ldmatrix lane geometry
    const int aRow  = wm * 32 + (lane & 15);
    const uint32_t aU    = (uint32_t)((lane >> 4) * 16);
    const uint32_t aMask = (uint32_t)((aRow & 7) << 4);
    const int bRow  = wn * 64 + ((lane >> 4) << 3) + (lane & 7);
    const uint32_t bU    = (uint32_t)(((lane >> 3) & 1) * 16);
    const uint32_t bMask = (uint32_t)((bRow & 7) << 4);

    issue(0);
    if (kTiles > 1) issue(1);

    for (int kt = 0; kt < kTiles; kt++) {
        if (kt + 1 < kTiles) cp_wait<1>(); else cp_wait<0>();
        __syncthreads();
        if (kt + STAGES - 1 < kTiles) issue(kt + STAGES - 1);

        const uint32_t so = (uint32_t)(kt % STAGES) * STAGE_B;
        #pragma unroll
        for (int ks = 0; ks < 4; ks++) {
            uint32_t afr[2][4];
            #pragma unroll
            for (int mi = 0; mi < 2; mi++) {
                uint32_t kb = ((uint32_t)(ks * 32) + aU) ^ aMask;
                ldsm4(afr[mi][0], afr[mi][1], afr[mi][2], afr[mi][3],
                      base + so + (uint32_t)((aRow + mi * 16) * 128) + kb);
            }
            uint32_t bfr[8][2];
            #pragma unroll
            for (int nj = 0; nj < 4; nj++) {
                uint32_t kb = ((uint32_t)(ks * 32) + bU) ^ bMask;
                ldsm4(bfr[2*nj][0], bfr[2*nj][1], bfr[2*nj+1][0], bfr[2*nj+1][1],
                      base + so + TILE_B + (uint32_t)((bRow + nj * 16) * 128) + kb);
            }
            #pragma unroll
            for (int mi = 0; mi < 2; mi++)
                #pragma unroll
                for (int ni = 0; ni < 8; ni++)
                    mma16816(acc[mi][ni], afr[mi], bfr[ni]);
        }
    }
}

// ============================================================================
// Prep kernels
// ============================================================================
__global__ __launch_bounds__(NTH)
void cvt_x_kernel(const float* __restrict__ X)
{
    size_t i = ((size_t)blockIdx.x * NTH + threadIdx.x) * 8;
    float4 a = *(const float4*)(X + i);
    float4 b = *(const float4*)(X + i + 4);
    __nv_bfloat162 o0 = __floats2bfloat162_rn(a.x, a.y);
    __nv_bfloat162 o1 = __floats2bfloat162_rn(a.z, a.w);
    __nv_bfloat162 o2 = __floats2bfloat162_rn(b.x, b.y);
    __nv_bfloat162 o3 = __floats2bfloat162_rn(b.z, b.w);
    uint4 pack;
    pack.x = *(uint32_t*)&o0; pack.y = *(uint32_t*)&o1;
    pack.z = *(uint32_t*)&o2; pack.w = *(uint32_t*)&o3;
    *(uint4*)(g_X + i) = pack;
}

__global__ __launch_bounds__(256)
void cvt_w_kernel(const float* __restrict__ Wq, const float* __restrict__ Wk,
                  const float* __restrict__ Wv, const float* __restrict__ Wg)
{
    const int z = blockIdx.z;
    const float* W = (z == 0) ? Wq : (z == 1) ? Wk : (z == 2) ? Wv : Wg;
    __shared__ __nv_bfloat16 t[32][33];
    const int n0 = blockIdx.x * 32, k0 = blockIdx.y * 32;
    const int tx = threadIdx.x & 31, ty = threadIdx.x >> 5;
    #pragma unroll
    for (int r = ty; r < 32; r += 8)
        t[r][tx] = __float2bfloat16(W[(size_t)(k0 + r) * DD + n0 + tx]);
    __syncthreads();
    #pragma unroll
    for (int r = ty; r < 32; r += 8)
        g_Wt[(size_t)z * DD * DD + (size_t)(n0 + r) * DD + k0 + tx] = t[tx][r];
}

__global__ __launch_bounds__(256)
void cvt_v_kernel()
{
    const int b = blockIdx.z;
    __shared__ __nv_bfloat16 t[32][33];
    const int j0 = blockIdx.x * 32, f0 = blockIdx.y * 32;
    const int tx = threadIdx.x & 31, ty = threadIdx.x >> 5;
    #pragma unroll
    for (int r = ty; r < 32; r += 8)
        t[r][tx] = g_V[((size_t)b * SQ + j0 + r) * DD + f0 + tx];
    __syncthreads();
    #pragma unroll
    for (int r = ty; r < 32; r += 8)
        g_Vt[(size_t)b * DD * SQ + (size_t)(f0 + r) * SQ + j0 + tx] = t[tx][r];
}

// ============================================================================
// Kernel 1: fused QKVG projections
// ============================================================================
__global__ __launch_bounds__(NTH, 2)
void proj_kernel(const float* __restrict__ bq, const float* __restrict__ bk,
                 const float* __restrict__ bv, const float* __restrict__ bg)
{
    const int zb = blockIdx.z;
    const int m0 = blockIdx.y * BM;
    const int n0 = blockIdx.x * BN;

    float acc[2][8][4] = {};
    gemm_main(g_X + (size_t)m0 * DD, DD,
              g_Wt + (size_t)zb * DD * DD + (size_t)n0 * DD, DD,
              DD / BK, acc);

    const float* bias = (zb == 0) ? bq : (zb == 1) ? bk : (zb == 2) ? bv : bg;
    const int lane = threadIdx.x & 31, warp = threadIdx.x >> 5;
    const int wm = warp & 3, wn = warp >> 2;
    const int g = lane >> 2, t = lane & 3;

    #pragma unroll
    for (int mi = 0; mi < 2; mi++) {
        #pragma unroll
        for (int ni = 0; ni < 8; ni++) {
            int row = m0 + wm * 32 + mi * 16 + g;
            int col = n0 + wn * 64 + ni * 8 + 2 * t;
            float b0 = bias[col], b1 = bias[col + 1];
            float c00 = acc[mi][ni][0] + b0, c01 = acc[mi][ni][1] + b1;
            float c10 = acc[mi][ni][2] + b0, c11 = acc[mi][ni][3] + b1;
            if (zb < 3) {
                __nv_bfloat16* O = (zb == 0) ? g_Q : (zb == 1) ? g_K : g_V;
                *(__nv_bfloat162*)&O[(size_t)row * DD + col]       = __floats2bfloat162_rn(c00, c01);
                *(__nv_bfloat162*)&O[(size_t)(row + 8) * DD + col] = __floats2bfloat162_rn(c10, c11);
            } else {
                float s00 = 1.f / (1.f + __expf(-c00));
                float s01 = 1.f / (1.f + __expf(-c01));
                float s10 = 1.f / (1.f + __expf(-c10));
                float s11 = 1.f / (1.f + __expf(-c11));
                *(float2*)&g_G[(size_t)row * DD + col]       = make_float2(s00, s01);
                *(float2*)&g_G[(size_t)(row + 8) * DD + col] = make_float2(s10, s11);
            }
        }
    }
}

// ============================================================================
// Kernel 2: scores = Q K^T / 32  (bf16 output)
// ============================================================================
__global__ __launch_bounds__(NTH, 2)
void scores_kernel()
{
    const int b  = blockIdx.z;
    const int m0 = blockIdx.y * BM;
    const int n0 = blockIdx.x * BN;

    float acc[2][8][4] = {};
    gemm_main(g_Q + (size_t)b * SQ * DD + (size_t)m0 * DD, DD,
              g_K + (size_t)b * SQ * DD + (size_t)n0 * DD, DD,
              DD / BK, acc);

    const int lane = threadIdx.x & 31, warp = threadIdx.x >> 5;
    const int wm = warp & 3, wn = warp >> 2;
    const int g = lane >> 2, t = lane & 3;

    const float sc = 0.03125f;
    #pragma unroll
    for (int mi = 0; mi < 2; mi++) {
        #pragma unroll
        for (int ni = 0; ni < 8; ni++) {
            int row = m0 + wm * 32 + mi * 16 + g;
            int col = n0 + wn * 64 + ni * 8 + 2 * t;
            size_t base = ((size_t)b * SQ + row) * SQ + col;
            *(__nv_bfloat162*)&g_S[base] =
                __floats2bfloat162_rn(acc[mi][ni][0] * sc, acc[mi][ni][1] * sc);
            *(__nv_bfloat162*)&g_S[base + 8ull * SQ] =
                __floats2bfloat162_rn(acc[mi][ni][2] * sc, acc[mi][ni][3] * sc);
        }
    }
}

// ============================================================================
// Kernel 3: row softmax over 4096 (bf16 in, bf16 out)
// ============================================================================
__global__ __launch_bounds__(NTH)
void softmax_kernel()
{
    const size_t row = blockIdx.x;
    const __nv_bfloat16* s = g_S + row * SQ;
    __nv_bfloat16* p = g_P + row * SQ;

    const int tid = threadIdx.x;
    const int lane = tid & 31, warp = tid >> 5;

    float v[16];
    float m = -1e30f;
    #pragma unroll
    for (int h = 0; h < 2; h++) {
        uint4 pk = *(const uint4*)(s + h * 2048 + tid * 8);
        const uint32_t w[4] = {pk.x, pk.y, pk.z, pk.w};
        #pragma unroll
        for (int q = 0; q < 4; q++) {
            __nv_bfloat162 bb = *(const __nv_bfloat162*)&w[q];
            float2 f = __bfloat1622float2(bb);
            v[h*8 + q*2] = f.x; v[h*8 + q*2 + 1] = f.y;
            m = fmaxf(m, fmaxf(f.x, f.y));
        }
    }

    __shared__ float red_m[8], red_s[8];
    #pragma unroll
    for (int o = 16; o; o >>= 1) m = fmaxf(m, __shfl_xor_sync(0xffffffffu, m, o));
    if (lane == 0) red_m[warp] = m;
    __syncthreads();
    float bm = -1e30f;
    #pragma unroll
    for (int i = 0; i < 8; i++) bm = fmaxf(bm, red_m[i]);

    float sum = 0.f;
    #pragma unroll
    for (int i = 0; i < 16; i++) { v[i] = __expf(v[i] - bm); sum += v[i]; }
    #pragma unroll
    for (int o = 16; o; o >>= 1) sum += __shfl_xor_sync(0xffffffffu, sum, o);
    if (lane == 0) red_s[warp] = sum;
    __syncthreads();
    float bs = 0.f;
    #pragma unroll
    for (int i = 0; i < 8; i++) bs += red_s[i];

    const float inv = 1.f / bs;
    #pragma unroll
    for (int h = 0; h < 2; h++) {
        uint4 pk;
        uint32_t* w = (uint32_t*)&pk;
        #pragma unroll
        for (int q = 0; q < 4; q++) {
            __nv_bfloat162 bb = __floats2bfloat162_rn(v[h*8 + q*2] * inv,
                                                      v[h*8 + q*2 + 1] * inv);
            w[q] = *(uint32_t*)&bb;
        }
        *(uint4*)(p + h * 2048 + tid * 8) = pk;
    }
}

// ============================================================================
// Kernel 4: out = P @ V ; y = g*out + x
// ============================================================================
__global__ __launch_bounds__(NTH, 2)
void out_kernel(const float* __restrict__ X, float* __restrict__ Y)
{
    const int b  = blockIdx.z;
    const int m0 = blockIdx.y * BM;
    const int n0 = blockIdx.x * BN;

    float acc[2][8][4] = {};
    gemm_main(g_P + (size_t)b * SQ * SQ + (size_t)m0 * SQ, SQ,
              g_Vt + (size_t)b * DD * SQ + (size_t)n0 * SQ, SQ,
              SQ / BK, acc);

    const int lane = threadIdx.x & 31, warp = threadIdx.x >> 5;
    const int wm = warp & 3, wn = warp >> 2;
    const int g = lane >> 2, t = lane & 3;

    #pragma unroll
    for (int mi = 0; mi < 2; mi++) {
        #pragma unroll
        for (int ni = 0; ni < 8; ni++) {
            int rl  = m0 + wm * 32 + mi * 16 + g;
            int col = n0 + wn * 64 + ni * 8 + 2 * t;
            size_t gr0 = ((size_t)b * SQ + rl) * DD + col;
            size_t gr1 = ((size_t)b * SQ + rl + 8) * DD + col;
            float2 gv0 = *(const float2*)&g_G[gr0];
            float2 xv0 = *(const float2*)&X[gr0];
            float2 gv1 = *(const float2*)&g_G[gr1];
            float2 xv1 = *(const float2*)&X[gr1];
            *(float2*)&Y[gr0] = make_float2(gv0.x * acc[mi][ni][0] + xv0.x,
                                            gv0.y * acc[mi][ni][1] + xv0.y);
            *(float2*)&Y[gr1] = make_float2(gv1.x * acc[mi][ni][2] + xv1.x,
                                            gv1.y * acc[mi][ni][3] + xv1.y);
        }
    }
}

// ============================================================================
extern "C" void kernel_launch(void* const* d_in, const int* in_sizes, int n_in,
                              void* d_out, int out_size)
{
    const float* x  = (const float*)d_in[0];
    const float* Wq = (const float*)d_in[1];
    const float* bq = (const float*)d_in[2];
    const float* Wk = (const float*)d_in[3];
    const float* bk = (const float*)d_in[4];
    const float* Wv = (const float*)d_in[5];
    const float* bv = (const float*)d_in[6];
    const float* Wg = (const float*)d_in[7];
    const float* bg = (const float*)d_in[8];
    float* y = (float*)d_out;

    static int attrDone = 0;
    if (!attrDone) {
        cudaFuncSetAttribute(proj_kernel,   cudaFuncAttributeMaxDynamicSharedMemorySize, SMEM_B);
        cudaFuncSetAttribute(scores_kernel, cudaFuncAttributeMaxDynamicSharedMemorySize, SMEM_B);
        cudaFuncSetAttribute(out_kernel,    cudaFuncAttributeMaxDynamicSharedMemorySize, SMEM_B);
        attrDone = 1;
    }

    dim3 blk(NTH);
    cvt_x_kernel<<<(MROWS * DD) / (NTH * 8), blk>>>(x);
    cvt_w_kernel<<<dim3(DD / 32, DD / 32, 4), dim3(256)>>>(Wq, Wk, Wv, Wg);
    proj_kernel<<<dim3(DD / BN, MROWS / BM, 4), blk, SMEM_B>>>(bq, bk, bv, bg);
    cvt_v_kernel<<<dim3(SQ / 32, DD / 32, BQ), dim3(256)>>>();
    scores_kernel<<<dim3(SQ / BN, SQ / BM, 4), blk, SMEM_B>>>();
    softmax_kernel<<<MROWS, blk>>>();
    out_kernel<<<dim3(DD / BN, SQ / BM, 4), blk, SMEM_B>>>(x, y);
}